// round 15
// baseline (speedup 1.0000x reference)
#include <cuda_runtime.h>
#include <cuda_fp16.h>
#include <stdint.h>
#include <math.h>

// ---------------- problem constants ----------------
#define BB   2
#define SS   2048
#define DIN  2048
#define NH   16
#define KVH  4
#define HD   128
#define GRP  (NH / KVH)            // 4
#define DOUT (NH * HD)             // 2048
#define DKV  (KVH * HD)            // 512
#define BS   (BB * SS)             // 4096
#define NQKV (DOUT + 2 * DKV)      // 3072

#define BM 128
#define BN 128
#define NTHR 256

// ---------------- fp16-single dense tiling (BK=64) ----------------
#define DKP 72                           // half row stride (64 + 8 pad)
#define DTILE (128 * DKP * 2)            // 18432 B per operand tile
#define DSTAGE (2 * DTILE)               // 36864 B
#define DSMEM (2 * DSTAGE)               // 73728 B -> 2 CTAs/SM
#define DBK 64

// ---------------- fused attention tiling ----------------
#define FBM 128
#define FBN 64
#define KSP 136                           // K half row stride (elems)
#define VSPH 72                           // V half row stride (elems)
#define QSP 136
#define KTILE (64 * KSP * 2)              // 17408 B (one of hi/lo)
#define VTILEH (128 * VSPH * 2)           // 18432 B
#define FSTAGE (2 * KTILE + VTILEH)       // 53248 B
#define FSMEM (3 * FSTAGE)                // 159744 B (3-stage)
#define QBYTES (128 * QSP * 2)

typedef __half hf;

// ---------------- device scratch ----------------
__device__ hf g_xh  [(size_t)BS * DIN];
__device__ hf g_WTh [(size_t)NQKV * DIN];            // q|k|v transposed fp16
__device__ hf g_WoTh[(size_t)DIN * DOUT];
__device__ hf g_qhmh[(size_t)BS * DOUT], g_qhml[(size_t)BS * DOUT];
__device__ hf g_khmh[(size_t)BS * DKV],  g_khml[(size_t)BS * DKV];
__device__ hf g_vTh [(size_t)BB * KVH * HD * SS];    // [b,kv,hd,tok]
__device__ hf g_ctxh[(size_t)BS * DOUT];

// ---------------- helpers ----------------
__device__ __forceinline__ uint32_t smem_u32(const void* p) {
    uint32_t a;
    asm("{ .reg .u64 t; cvta.to.shared.u64 t, %1; cvt.u32.u64 %0, t; }"
        : "=r"(a) : "l"(p));
    return a;
}
__device__ __forceinline__ uint32_t pack_h(hf a, hf b) {
    uint16_t ua = *reinterpret_cast<uint16_t*>(&a);
    uint16_t ub = *reinterpret_cast<uint16_t*>(&b);
    return (uint32_t)ua | ((uint32_t)ub << 16);
}
__device__ __forceinline__ void split2h(float x, float y, hf* hi, hf* lo,
                                        size_t idx) {
    hf h0 = __float2half_rn(x), h1 = __float2half_rn(y);
    hf l0 = __float2half_rn(x - __half2float(h0));
    hf l1 = __float2half_rn(y - __half2float(h1));
    *reinterpret_cast<uint32_t*>(hi + idx) = pack_h(h0, h1);
    *reinterpret_cast<uint32_t*>(lo + idx) = pack_h(l0, l1);
}
__device__ __forceinline__ void cpasync16(uint32_t dst, const void* src) {
    asm volatile("cp.async.cg.shared.global [%0], [%1], 16;"
                 :: "r"(dst), "l"(src));
}
__device__ __forceinline__ void ldm4(uint32_t* d, uint32_t addr) {
    asm volatile("ldmatrix.sync.aligned.m8n8.x4.shared.b16 {%0,%1,%2,%3}, [%4];"
                 : "=r"(d[0]), "=r"(d[1]), "=r"(d[2]), "=r"(d[3]) : "r"(addr));
}
__device__ __forceinline__ void mma_f16(float* c, const uint32_t* a, const uint32_t* b) {
    asm volatile(
        "mma.sync.aligned.m16n8k16.row.col.f32.f16.f16.f32 "
        "{%0,%1,%2,%3}, {%4,%5,%6,%7}, {%8,%9}, {%0,%1,%2,%3};"
        : "+f"(c[0]), "+f"(c[1]), "+f"(c[2]), "+f"(c[3])
        : "r"(a[0]), "r"(a[1]), "r"(a[2]), "r"(a[3]), "r"(b[0]), "r"(b[1]));
}

// ---------------- fp16-single NT mainloop (BK=64, 2-stage) --------------
__device__ __forceinline__ void mma_compute_f16(
    char* dyn, const hf* __restrict__ A, const hf* __restrict__ B,
    int ld, int K, int m0, int n0, float acc[4][4][4])
{
    const uint32_t sb = smem_u32(dyn);
    const int tid  = threadIdx.x;
    const int lane = tid & 31;
    const int wid  = tid >> 5;
    const int wm   = wid & 1;
    const int wn   = wid >> 1;

#pragma unroll
    for (int i = 0; i < 4; i++)
#pragma unroll
        for (int j = 0; j < 4; j++)
#pragma unroll
            for (int k = 0; k < 4; k++) acc[i][j][k] = 0.f;

    const uint32_t aoff =
        (uint32_t)(((wm * 64 + (lane & 15)) * DKP + ((lane >> 4) * 8)) * 2);
    const uint32_t boff =
        (uint32_t)(((wn * 32 + ((lane >> 4) * 8) + (lane & 7)) * DKP +
                    (((lane >> 3) & 1) * 8)) * 2);

    const int frow = tid >> 1;                 // 0..127
    const int fseg = (tid & 1) * 32;           // halves (0 or 32)
    const int nch = K / DBK;

    auto fill = [&](int ch) {
        const uint32_t st = sb + (uint32_t)(ch & 1) * DSTAGE;
        const int k0 = ch * DBK;
        const uint32_t so = (uint32_t)(frow * DKP + fseg) * 2;
        const size_t ai = (size_t)(m0 + frow) * ld + k0 + fseg;
        const size_t bi = (size_t)(n0 + frow) * ld + k0 + fseg;
#pragma unroll
        for (int q = 0; q < 4; q++) {
            cpasync16(st + so + q * 16, A + ai + q * 8);
            cpasync16(st + DTILE + so + q * 16, B + bi + q * 8);
        }
        asm volatile("cp.async.commit_group;");
    };

    fill(0);
    for (int ch = 0; ch < nch; ch++) {
        if (ch + 1 < nch) {
            fill(ch + 1);
            asm volatile("cp.async.wait_group 1;");
        } else {
            asm volatile("cp.async.wait_group 0;");
        }
        __syncthreads();

        const uint32_t base = sb + (uint32_t)(ch & 1) * DSTAGE;
        const uint32_t aB = base + aoff;
        const uint32_t bB = base + DTILE + boff;
#pragma unroll
        for (int ks = 0; ks < 4; ks++) {
            uint32_t bh[8];
            ldm4(bh + 0, bB + ks * 32);
            ldm4(bh + 4, bB + 16 * DKP * 2 + ks * 32);
#pragma unroll
            for (int mt = 0; mt < 4; mt++) {
                uint32_t ah[4];
                ldm4(ah, aB + mt * 16 * DKP * 2 + ks * 32);
#pragma unroll
                for (int nt = 0; nt < 4; nt++)
                    mma_f16(acc[mt][nt], ah, &bh[nt * 2]);
            }
        }
        __syncthreads();
    }
}

// ---------------- O-projection (fp16 single) ----------------
__global__ void __launch_bounds__(NTHR, 2)
k_mma_o(const hf* __restrict__ A, const hf* __restrict__ B,
        float* __restrict__ C)
{
    extern __shared__ char dyn[];
    const int m0 = blockIdx.y * BM, n0 = blockIdx.x * BN;
    float acc[4][4][4];
    mma_compute_f16(dyn, A, B, DOUT, DOUT, m0, n0, acc);

    const int lane = threadIdx.x & 31, wid = threadIdx.x >> 5;
    const int wm = wid & 1, wn = wid >> 1;
    const int g = lane >> 2, cq = lane & 3;
#pragma unroll
    for (int mt = 0; mt < 4; mt++)
#pragma unroll
        for (int half = 0; half < 2; half++) {
            const int row = m0 + wm * 64 + mt * 16 + g + half * 8;
#pragma unroll
            for (int nt = 0; nt < 4; nt++) {
                const int col = n0 + wn * 32 + nt * 8 + cq * 2;
                *reinterpret_cast<float2*>(C + (size_t)row * DIN + col) =
                    make_float2(acc[mt][nt][half * 2 + 0],
                                acc[mt][nt][half * 2 + 1]);
            }
        }
}

// ---------------- merged QKV fp16 GEMM + fused epilogues ----------------
__global__ void __launch_bounds__(NTHR, 2)
k_mma_qkv(const hf* __restrict__ xh, const hf* __restrict__ W,
          hf* __restrict__ vT,
          hf* __restrict__ qhmh, hf* __restrict__ qhml,
          hf* __restrict__ khmh, hf* __restrict__ khml,
          const float* __restrict__ cosb, const float* __restrict__ sinb,
          const float* __restrict__ qs, const float* __restrict__ ks)
{
    extern __shared__ char dyn[];
    const int m0 = blockIdx.y * BM, n0 = blockIdx.x * BN;
    float acc[4][4][4];
    mma_compute_f16(dyn, xh, W, DIN, DIN, m0, n0, acc);

    const int lane = threadIdx.x & 31, wid = threadIdx.x >> 5;
    const int wm = wid & 1, wn = wid >> 1;

    if (n0 >= DOUT + DKV) {
        // ---- V tile: smem transpose -> vT[kv][hd][tok] fp16 ----
        const int kv = (n0 - DOUT - DKV) / HD;
        float* stg = reinterpret_cast<float*>(dyn);   // [128 tok][133]
#pragma unroll
        for (int mt = 0; mt < 4; mt++)
#pragma unroll
            for (int half = 0; half < 2; half++) {
                const int rl = wm * 64 + mt * 16 + (lane >> 2) + half * 8;
#pragma unroll
                for (int nt = 0; nt < 4; nt++) {
                    const int c = wn * 32 + nt * 8 + (lane & 3) * 2;
                    stg[rl * 133 + c]     = acc[mt][nt][half * 2 + 0];
                    stg[rl * 133 + c + 1] = acc[mt][nt][half * 2 + 1];
                }
            }
        __syncthreads();
        const int b = m0 >> 11, pos0 = m0 & (SS - 1);
        hf* dst = vT + (size_t)(b * KVH + kv) * HD * SS + pos0;
#pragma unroll
        for (int rr = 0; rr < 16; rr++) {
            const int r = wid * 16 + rr;              // hd row
            uint2 v;
            v.x = pack_h(__float2half_rn(stg[(lane * 4 + 0) * 133 + r]),
                         __float2half_rn(stg[(lane * 4 + 1) * 133 + r]));
            v.y = pack_h(__float2half_rn(stg[(lane * 4 + 2) * 133 + r]),
                         __float2half_rn(stg[(lane * 4 + 3) * 133 + r]));
            *reinterpret_cast<uint2*>(dst + (size_t)r * SS + lane * 4) = v;
        }
        return;
    }

    // ---- Q/K tile: rmsnorm + rope + fp16 hi/lo split, head-major ----
    const bool isQ = (n0 < DOUT);
    const float* scale = isQ ? qs : ks;
    hf* oh = isQ ? qhmh : khmh;
    hf* ol = isQ ? qhml : khml;
    const int nheads = isQ ? NH : KVH;
    const int h = (isQ ? n0 : (n0 - DOUT)) / HD;
    const float alpha = isQ ? 0.08838834764831845f : 1.0f;

    float* rsum = reinterpret_cast<float*>(dyn);                 // [128][4]
    float* stg  = reinterpret_cast<float*>(dyn + 2048);          // [128][132]

#pragma unroll
    for (int mt = 0; mt < 4; mt++)
#pragma unroll
        for (int half = 0; half < 2; half++) {
            const int rl = wm * 64 + mt * 16 + (lane >> 2) + half * 8;
            float part = 0.f;
#pragma unroll
            for (int nt = 0; nt < 4; nt++) {
                const float vx = acc[mt][nt][half * 2 + 0];
                const float vy = acc[mt][nt][half * 2 + 1];
                part += vx * vx + vy * vy;
            }
            part += __shfl_xor_sync(0xffffffffu, part, 1);
            part += __shfl_xor_sync(0xffffffffu, part, 2);
            if ((lane & 3) == 0) rsum[rl * 4 + wn] = part;
        }
    __syncthreads();

#pragma unroll
    for (int mt = 0; mt < 4; mt++)
#pragma unroll
        for (int half = 0; half < 2; half++) {
            const int rl = wm * 64 + mt * 16 + (lane >> 2) + half * 8;
            const float tot = rsum[rl * 4 + 0] + rsum[rl * 4 + 1] +
                              rsum[rl * 4 + 2] + rsum[rl * 4 + 3];
            const float rinv = rsqrtf(tot * (1.0f / HD) + 1e-6f) * alpha;
#pragma unroll
            for (int nt = 0; nt < 4; nt++) {
                const int c = wn * 32 + nt * 8 + (lane & 3) * 2;
                stg[rl * 132 + c]     = acc[mt][nt][half * 2 + 0] * rinv * scale[c];
                stg[rl * 132 + c + 1] = acc[mt][nt][half * 2 + 1] * rinv * scale[c + 1];
            }
        }
    __syncthreads();

#pragma unroll
    for (int mt = 0; mt < 4; mt++)
#pragma unroll
        for (int half = 0; half < 2; half++) {
            const int rl = wm * 64 + mt * 16 + (lane >> 2) + half * 8;
            const int row = m0 + rl;
            const int b = row >> 11, pos = row & (SS - 1);
#pragma unroll
            for (int nt = 0; nt < 4; nt++) {
                const int c = wn * 32 + nt * 8 + (lane & 3) * 2;
                const float xn0 = stg[rl * 132 + c];
                const float xn1 = stg[rl * 132 + c + 1];
                const int p = (c + 64) & 127;
                const float s0 = stg[rl * 132 + p];
                const float s1 = stg[rl * 132 + p + 1];
                const float rot0 = (c < 64) ? -s0 : s0;
                const float rot1 = (c < 64) ? -s1 : s1;
                const float o0 = xn0 * cosb[pos * HD + c]     + rot0 * sinb[pos * HD + c];
                const float o1 = xn1 * cosb[pos * HD + c + 1] + rot1 * sinb[pos * HD + c + 1];
                const size_t oi = ((size_t)(b * nheads + h) * SS + pos) * HD + c;
                split2h(o0, o1, oh, ol, oi);
            }
        }
}

// ---------------- fused flash attention (QK fp16x3, PV fp16x1) ----------
__global__ void __launch_bounds__(256, 1)
k_attn(const hf* __restrict__ qhp, const hf* __restrict__ qlp,
       const hf* __restrict__ khp, const hf* __restrict__ klp,
       const hf* __restrict__ vtp,
       hf* __restrict__ ctxh)
{
    extern __shared__ char dyn[];
    const uint32_t sb = smem_u32(dyn);
    hf* VsH = reinterpret_cast<hf*>(dyn);
    const int tid = threadIdx.x, lane = tid & 31, w = tid >> 5;
    const int bh = blockIdx.y, b = bh / NH, h = bh % NH;
    const int kvh = (bh % NH) / GRP;
    const int m0 = ((int)gridDim.x - 1 - (int)blockIdx.x) * FBM;
    const size_t qo = (size_t)bh * SS * HD;
    const size_t ko = (size_t)(b * KVH + kvh) * SS * HD;
    const size_t vo = (size_t)(b * KVH + kvh) * HD * SS;

#pragma unroll
    for (int it = 0; it < 8; it++) {
        const int c = tid + it * 256;
        const int row = c >> 4, col = (c & 15) * 8;
        const size_t gi = qo + (size_t)(m0 + row) * HD + col;
        cpasync16(sb + (uint32_t)(row * QSP + col) * 2, qhp + gi);
        cpasync16(sb + QBYTES + (uint32_t)(row * QSP + col) * 2, qlp + gi);
    }
    asm volatile("cp.async.commit_group;");
    asm volatile("cp.async.wait_group 0;");
    __syncthreads();

    uint32_t qfh[8][4], qfl[8][4];
    {
        const uint32_t ab = sb +
            (uint32_t)(((w * 16 + (lane & 15)) * QSP + (lane >> 4) * 8) * 2);
#pragma unroll
        for (int kk = 0; kk < 8; kk++) {
            ldm4(qfh[kk], ab + kk * 32);
            ldm4(qfl[kk], ab + QBYTES + kk * 32);
        }
    }
    __syncthreads();

    const int nb = m0 / FBN + 2;

    auto load_kv = [&](int i) {
        if (i < nb) {
            const int n0 = i * FBN;
            const uint32_t bufb = sb + (uint32_t)(i % 3) * FSTAGE;
#pragma unroll
            for (int it = 0; it < 4; it++) {
                const int c = tid + it * 256;
                const int krow = c >> 4, kcol = (c & 15) * 8;
                const size_t gk = ko + (size_t)(n0 + krow) * HD + kcol;
                cpasync16(bufb + (uint32_t)(krow * KSP + kcol) * 2, khp + gk);
                cpasync16(bufb + KTILE + (uint32_t)(krow * KSP + kcol) * 2, klp + gk);
                const int vrow = c >> 3, vc8 = (c & 7) * 8;
                cpasync16(bufb + 2 * KTILE + (uint32_t)(vrow * VSPH + vc8) * 2,
                          vtp + vo + (size_t)vrow * SS + n0 + vc8);
            }
        }
        asm volatile("cp.async.commit_group;");
    };

    load_kv(0);
    load_kv(1);

    float ctxa[16][4];
#pragma unroll
    for (int j = 0; j < 16; j++)
#pragma unroll
        for (int e = 0; e < 4; e++) ctxa[j][e] = 0.f;
    float mrow0 = -1e30f, mrow8 = -1e30f, lrow0 = 0.f, lrow8 = 0.f;

    const uint32_t kboff =
        (uint32_t)((((lane >> 4) * 8 + (lane & 7)) * KSP + ((lane >> 3) & 1) * 8) * 2);
    const int r0g = m0 + w * 16 + (lane >> 2);
    const int cquad = 2 * (lane & 3);
    const int g = lane >> 2;

    for (int i = 0; i < nb; i++) {
        asm volatile("cp.async.wait_group 1;");
        __syncthreads();
        load_kv(i + 2);                       // prefetch overlaps compute
        const uint32_t base = sb + (uint32_t)(i % 3) * FSTAGE;
        const int vwH = (int)((i % 3) * (FSTAGE / 2)) + (2 * KTILE) / 2;
        const int n0 = i * FBN;

        float s[8][4];
#pragma unroll
        for (int j = 0; j < 8; j++)
#pragma unroll
            for (int e = 0; e < 4; e++) s[j][e] = 0.f;

        const uint32_t kb = base + kboff;
#pragma unroll
        for (int kk = 0; kk < 8; kk++) {
#pragma unroll
            for (int ng = 0; ng < 4; ng++) {
                uint32_t bh4[4], bl4[4];
                const uint32_t a = kb + (uint32_t)(ng * 16 * KSP * 2) + kk * 32;
                ldm4(bh4, a);
                ldm4(bl4, a + KTILE);
                mma_f16(s[2 * ng + 0], qfh[kk], bh4 + 0);
                mma_f16(s[2 * ng + 0], qfl[kk], bh4 + 0);
                mma_f16(s[2 * ng + 0], qfh[kk], bl4 + 0);
                mma_f16(s[2 * ng + 1], qfh[kk], bh4 + 2);
                mma_f16(s[2 * ng + 1], qfl[kk], bh4 + 2);
                mma_f16(s[2 * ng + 1], qfh[kk], bl4 + 2);
            }
        }

        if (n0 + FBN - 1 > m0) {
#pragma unroll
            for (int j = 0; j < 8; j++) {
                const int col = n0 + j * 8 + cquad;
                if (col > r0g)         s[j][0] = -1e30f;
                if (col + 1 > r0g)     s[j][1] = -1e30f;
                if (col > r0g + 8)     s[j][2] = -1e30f;
                if (col + 1 > r0g + 8) s[j][3] = -1e30f;
            }
        }

        float mx0 = -1e30f, mx8 = -1e30f;
#pragma unroll
        for (int j = 0; j < 8; j++) {
            mx0 = fmaxf(mx0, fmaxf(s[j][0], s[j][1]));
            mx8 = fmaxf(mx8, fmaxf(s[j][2], s[j][3]));
        }
        mx0 = fmaxf(mx0, __shfl_xor_sync(0xffffffffu, mx0, 1));
        mx0 = fmaxf(mx0, __shfl_xor_sync(0xffffffffu, mx0, 2));
        mx8 = fmaxf(mx8, __shfl_xor_sync(0xffffffffu, mx8, 1));
        mx8 = fmaxf(mx8, __shfl_xor_sync(0xffffffffu, mx8, 2));

        const float mn0 = fmaxf(mrow0, mx0), mn8 = fmaxf(mrow8, mx8);
        const float sc0 = __expf(mrow0 - mn0), sc8 = __expf(mrow8 - mn8);
        mrow0 = mn0; mrow8 = mn8;

        float sum0 = 0.f, sum8 = 0.f;
        uint32_t ph[8][2];
#pragma unroll
        for (int j = 0; j < 8; j++) {
            const float e0 = __expf(s[j][0] - mn0);
            const float e1 = __expf(s[j][1] - mn0);
            const float e2 = __expf(s[j][2] - mn8);
            const float e3 = __expf(s[j][3] - mn8);
            sum0 += e0 + e1; sum8 += e2 + e3;
            ph[j][0] = pack_h(__float2half_rn(e0), __float2half_rn(e1));
            ph[j][1] = pack_h(__float2half_rn(e2), __float2half_rn(e3));
        }
        sum0 += __shfl_xor_sync(0xffffffffu, sum0, 1);
        sum0 += __shfl_xor_sync(0xffffffffu, sum0, 2);
        sum8 += __shfl_xor_sync(0xffffffffu, sum8, 1);
        sum8 += __shfl_xor_sync(0xffffffffu, sum8, 2);
        lrow0 = lrow0 * sc0 + sum0;
        lrow8 = lrow8 * sc8 + sum8;

#pragma unroll
        for (int j = 0; j < 16; j++) {
            ctxa[j][0] *= sc0; ctxa[j][1] *= sc0;
            ctxa[j][2] *= sc8; ctxa[j][3] *= sc8;
        }

        // PV fp16 single-term: A = exp frags, B = V[hd][tok] natural layout
#pragma unroll
        for (int t = 0; t < 4; t++) {
            const uint32_t pa[4] = { ph[2 * t][0], ph[2 * t][1],
                                     ph[2 * t + 1][0], ph[2 * t + 1][1] };
#pragma unroll
            for (int nt = 0; nt < 16; nt++) {
                const int vi = vwH + (nt * 8 + g) * VSPH + t * 16 + cquad;
                uint32_t vb[2];
                vb[0] = *reinterpret_cast<const uint32_t*>(VsH + vi);
                vb[1] = *reinterpret_cast<const uint32_t*>(VsH + vi + 8);
                mma_f16(ctxa[nt], pa, vb);
            }
        }
    }

    // epilogue: normalize + fp16 store (O-proj operand)
    const float inv0 = 1.0f / lrow0, inv8 = 1.0f / lrow8;
    const int r0 = m0 + w * 16 + (lane >> 2);
#pragma unroll
    for (int j = 0; j < 16; j++) {
        const int col = h * HD + j * 8 + cquad;
        const size_t i0 = ((size_t)b * SS + r0) * DOUT + col;
        const size_t i8 = ((size_t)b * SS + r0 + 8) * DOUT + col;
        *reinterpret_cast<uint32_t*>(ctxh + i0) =
            pack_h(__float2half_rn(ctxa[j][0] * inv0),
                   __float2half_rn(ctxa[j][1] * inv0));
        *reinterpret_cast<uint32_t*>(ctxh + i8) =
            pack_h(__float2half_rn(ctxa[j][2] * inv8),
                   __float2half_rn(ctxa[j][3] * inv8));
    }
}

// ---------------- prep kernels ----------------
__global__ void k_xhalf(const float* __restrict__ in, hf* __restrict__ outp,
                        int n)
{
    const int i = (blockIdx.x * blockDim.x + threadIdx.x) * 2;
    if (i < n) {
        float2 v = *reinterpret_cast<const float2*>(in + i);
        *reinterpret_cast<uint32_t*>(outp + i) =
            pack_h(__float2half_rn(v.x), __float2half_rn(v.y));
    }
}

// merged weight transposes -> fp16 (flat grid over Wq, Wk, Wv, Wo)
__global__ void k_wprep(const float* __restrict__ Wq, const float* __restrict__ Wk,
                        const float* __restrict__ Wv, const float* __restrict__ Wo,
                        hf* __restrict__ WTh, hf* __restrict__ WoTh)
{
    __shared__ float t[32][33];
    int bid = blockIdx.x;
    const float* src; hf* dst; int ldin, ldout, nbx;
    if (bid < 4096)      { src = Wq; dst = WTh; ldin = DOUT; ldout = DIN; nbx = 64; }
    else if (bid < 5120) { bid -= 4096; src = Wk; dst = WTh + (size_t)DOUT * DIN;
                           ldin = DKV; ldout = DIN; nbx = 16; }
    else if (bid < 6144) { bid -= 5120; src = Wv; dst = WTh + (size_t)(DOUT + DKV) * DIN;
                           ldin = DKV; ldout = DIN; nbx = 16; }
    else                 { bid -= 6144; src = Wo; dst = WoTh; ldin = DIN; ldout = DOUT; nbx = 64; }
    const int c0 = (bid % nbx) * 32, r0 = (bid / nbx) * 32;
    const int tx = threadIdx.x, ty = threadIdx.y;
#pragma unroll
    for (int i = 0; i < 32; i += 8)
        t[ty + i][tx] = src[(size_t)(r0 + ty + i) * ldin + c0 + tx];
    __syncthreads();
#pragma unroll
    for (int i = 0; i < 32; i += 8)
        dst[(size_t)(c0 + ty + i) * ldout + r0 + tx] =
            __float2half_rn(t[tx][ty + i]);
}

// ---------------- launch ----------------
extern "C" void kernel_launch(void* const* d_in, const int* in_sizes, int n_in,
                              void* d_out, int out_size)
{
    const float* x    = (const float*)d_in[0];
    const float* cosb = (const float*)d_in[2];
    const float* sinb = (const float*)d_in[3];
    const float* Wq   = (const float*)d_in[4];
    const float* Wk   = (const float*)d_in[5];
    const float* Wv   = (const float*)d_in[6];
    const float* Wo   = (const float*)d_in[7];
    const float* qs   = (const float*)d_in[8];
    const float* ks   = (const float*)d_in[9];
    float* out = (float*)d_out;

    hf *xh, *WTh, *WoTh, *qhmh, *qhml, *khmh, *khml, *vTh, *ctxh;
    cudaGetSymbolAddress((void**)&xh,   g_xh);
    cudaGetSymbolAddress((void**)&WTh,  g_WTh);
    cudaGetSymbolAddress((void**)&WoTh, g_WoTh);
    cudaGetSymbolAddress((void**)&qhmh, g_qhmh);
    cudaGetSymbolAddress((void**)&qhml, g_qhml);
    cudaGetSymbolAddress((void**)&khmh, g_khmh);
    cudaGetSymbolAddress((void**)&khml, g_khml);
    cudaGetSymbolAddress((void**)&vTh,  g_vTh);
    cudaGetSymbolAddress((void**)&ctxh, g_ctxh);

    cudaFuncSetAttribute(k_mma_qkv, cudaFuncAttributeMaxDynamicSharedMemorySize, DSMEM);
    cudaFuncSetAttribute(k_mma_o,   cudaFuncAttributeMaxDynamicSharedMemorySize, DSMEM);
    cudaFuncSetAttribute(k_attn,    cudaFuncAttributeMaxDynamicSharedMemorySize, FSMEM);

    // Prep: merged fp16 weight transposes + fp16 round of x
    k_wprep<<<10240, dim3(32, 8)>>>(Wq, Wk, Wv, Wo, WTh, WoTh);
    k_xhalf<<<(BS * DIN / 2 + 255) / 256, 256>>>(x, xh, BS * DIN);

    // Merged QKV projection (fp16 single): Q/K -> normrope+split, V -> vT
    k_mma_qkv<<<dim3(NQKV / BN, BS / BM), NTHR, DSMEM>>>(
        xh, WTh, vTh, qhmh, qhml, khmh, khml, cosb, sinb, qs, ks);

    // Fused flash attention (QK fp16x3, PV fp16x1; 3-stage pipeline)
    k_attn<<<dim3(SS / FBM, BB * NH), 256, FSMEM>>>(
        qhmh, qhml, khmh, khml, vTh, ctxh);

    // Output projection (fp16 single)
    k_mma_o<<<dim3(DIN / BN, BS / BM), NTHR, DSMEM>>>(ctxh, WoTh, out);
}

// round 16
// speedup vs baseline: 1.1344x; 1.1344x over previous
#include <cuda_runtime.h>
#include <cuda_fp16.h>
#include <stdint.h>
#include <math.h>

// ---------------- problem constants ----------------
#define BB   2
#define SS   2048
#define DIN  2048
#define NH   16
#define KVH  4
#define HD   128
#define GRP  (NH / KVH)            // 4
#define DOUT (NH * HD)             // 2048
#define DKV  (KVH * HD)            // 512
#define BS   (BB * SS)             // 4096
#define NQKV (DOUT + 2 * DKV)      // 3072

#define BM 128
#define BN 128
#define NTHR 256

// ---------------- fp16-single dense tiling (BK=32, 3-stage) -------------
#define DKP 40                           // half row stride
#define DTILE (128 * DKP * 2)            // 10240 B per operand tile
#define DSTAGE (2 * DTILE)               // 20480 B
#define DSMEM (3 * DSTAGE)               // 61440 B -> 2 CTAs/SM
#define QKV_SMEM 69632                   // epilogue staging needs more
#define DBK 32

// ---------------- fused attention tiling ----------------
#define FBM 128
#define FBN 64
#define KSP 136                           // K half row stride (elems)
#define VSPH 72                           // V half row stride (elems)
#define QSP 136
#define KTILE (64 * KSP * 2)              // 17408 B (one of hi/lo)
#define VTILEH (128 * VSPH * 2)           // 18432 B
#define FSTAGE (2 * KTILE + VTILEH)       // 53248 B
#define FSMEM (3 * FSTAGE)                // 159744 B (3-stage)
#define QBYTES (128 * QSP * 2)

typedef __half hf;

// ---------------- device scratch ----------------
__device__ hf g_xh  [(size_t)BS * DIN];
__device__ hf g_WTh [(size_t)NQKV * DIN];            // q|k|v transposed fp16
__device__ hf g_WoTh[(size_t)DIN * DOUT];
__device__ hf g_qhmh[(size_t)BS * DOUT], g_qhml[(size_t)BS * DOUT];
__device__ hf g_khmh[(size_t)BS * DKV],  g_khml[(size_t)BS * DKV];
__device__ hf g_vTh [(size_t)BB * KVH * HD * SS];    // [b,kv,hd,tok]
__device__ hf g_ctxh[(size_t)BS * DOUT];

// ---------------- helpers ----------------
__device__ __forceinline__ uint32_t smem_u32(const void* p) {
    uint32_t a;
    asm("{ .reg .u64 t; cvta.to.shared.u64 t, %1; cvt.u32.u64 %0, t; }"
        : "=r"(a) : "l"(p));
    return a;
}
__device__ __forceinline__ uint32_t pack_h(hf a, hf b) {
    uint16_t ua = *reinterpret_cast<uint16_t*>(&a);
    uint16_t ub = *reinterpret_cast<uint16_t*>(&b);
    return (uint32_t)ua | ((uint32_t)ub << 16);
}
__device__ __forceinline__ void split2h(float x, float y, hf* hi, hf* lo,
                                        size_t idx) {
    hf h0 = __float2half_rn(x), h1 = __float2half_rn(y);
    hf l0 = __float2half_rn(x - __half2float(h0));
    hf l1 = __float2half_rn(y - __half2float(h1));
    *reinterpret_cast<uint32_t*>(hi + idx) = pack_h(h0, h1);
    *reinterpret_cast<uint32_t*>(lo + idx) = pack_h(l0, l1);
}
__device__ __forceinline__ void cpasync16(uint32_t dst, const void* src) {
    asm volatile("cp.async.cg.shared.global [%0], [%1], 16;"
                 :: "r"(dst), "l"(src));
}
__device__ __forceinline__ void ldm4(uint32_t* d, uint32_t addr) {
    asm volatile("ldmatrix.sync.aligned.m8n8.x4.shared.b16 {%0,%1,%2,%3}, [%4];"
                 : "=r"(d[0]), "=r"(d[1]), "=r"(d[2]), "=r"(d[3]) : "r"(addr));
}
__device__ __forceinline__ void mma_f16(float* c, const uint32_t* a, const uint32_t* b) {
    asm volatile(
        "mma.sync.aligned.m16n8k16.row.col.f32.f16.f16.f32 "
        "{%0,%1,%2,%3}, {%4,%5,%6,%7}, {%8,%9}, {%0,%1,%2,%3};"
        : "+f"(c[0]), "+f"(c[1]), "+f"(c[2]), "+f"(c[3])
        : "r"(a[0]), "r"(a[1]), "r"(a[2]), "r"(a[3]), "r"(b[0]), "r"(b[1]));
}

// ---------------- fp16-single NT mainloop (BK=32, 3-stage, 1 sync) ------
__device__ __forceinline__ void mma_compute_f16(
    char* dyn, const hf* __restrict__ A, const hf* __restrict__ B,
    int ld, int K, int m0, int n0, float acc[4][4][4])
{
    const uint32_t sb = smem_u32(dyn);
    const int tid  = threadIdx.x;
    const int lane = tid & 31;
    const int wid  = tid >> 5;
    const int wm   = wid & 1;
    const int wn   = wid >> 1;

#pragma unroll
    for (int i = 0; i < 4; i++)
#pragma unroll
        for (int j = 0; j < 4; j++)
#pragma unroll
            for (int k = 0; k < 4; k++) acc[i][j][k] = 0.f;

    const uint32_t aoff =
        (uint32_t)(((wm * 64 + (lane & 15)) * DKP + ((lane >> 4) * 8)) * 2);
    const uint32_t boff =
        (uint32_t)(((wn * 32 + ((lane >> 4) * 8) + (lane & 7)) * DKP +
                    (((lane >> 3) & 1) * 8)) * 2);

    const int frow = tid >> 1;
    const int fseg = (tid & 1) * 16;
    const int nch = K / DBK;

    auto fill = [&](int ch) {
        if (ch < nch) {
            const uint32_t st = sb + (uint32_t)(ch % 3) * DSTAGE;
            const int k0 = ch * DBK;
            const uint32_t so = (uint32_t)(frow * DKP + fseg) * 2;
            const size_t ai = (size_t)(m0 + frow) * ld + k0 + fseg;
            const size_t bi = (size_t)(n0 + frow) * ld + k0 + fseg;
            cpasync16(st + so, A + ai);
            cpasync16(st + so + 16, A + ai + 8);
            cpasync16(st + DTILE + so, B + bi);
            cpasync16(st + DTILE + so + 16, B + bi + 8);
        }
        asm volatile("cp.async.commit_group;");
    };

    fill(0);
    fill(1);
    for (int ch = 0; ch < nch; ch++) {
        asm volatile("cp.async.wait_group 1;");
        __syncthreads();
        fill(ch + 2);                     // prefetch overlaps compute

        const uint32_t base = sb + (uint32_t)(ch % 3) * DSTAGE;
        const uint32_t aB = base + aoff;
        const uint32_t bB = base + DTILE + boff;
#pragma unroll
        for (int ks = 0; ks < 2; ks++) {
            uint32_t bh[8];
            ldm4(bh + 0, bB + ks * 32);
            ldm4(bh + 4, bB + 16 * DKP * 2 + ks * 32);
#pragma unroll
            for (int mt = 0; mt < 4; mt++) {
                uint32_t ah[4];
                ldm4(ah, aB + mt * 16 * DKP * 2 + ks * 32);
#pragma unroll
                for (int nt = 0; nt < 4; nt++)
                    mma_f16(acc[mt][nt], ah, &bh[nt * 2]);
            }
        }
    }
    __syncthreads();                       // protect smem reuse by epilogues
}

// ---------------- O-projection (fp16 single) ----------------
__global__ void __launch_bounds__(NTHR, 2)
k_mma_o(const hf* __restrict__ A, const hf* __restrict__ B,
        float* __restrict__ C)
{
    extern __shared__ char dyn[];
    const int m0 = blockIdx.y * BM, n0 = blockIdx.x * BN;
    float acc[4][4][4];
    mma_compute_f16(dyn, A, B, DOUT, DOUT, m0, n0, acc);

    const int lane = threadIdx.x & 31, wid = threadIdx.x >> 5;
    const int wm = wid & 1, wn = wid >> 1;
    const int g = lane >> 2, cq = lane & 3;
#pragma unroll
    for (int mt = 0; mt < 4; mt++)
#pragma unroll
        for (int half = 0; half < 2; half++) {
            const int row = m0 + wm * 64 + mt * 16 + g + half * 8;
#pragma unroll
            for (int nt = 0; nt < 4; nt++) {
                const int col = n0 + wn * 32 + nt * 8 + cq * 2;
                *reinterpret_cast<float2*>(C + (size_t)row * DIN + col) =
                    make_float2(acc[mt][nt][half * 2 + 0],
                                acc[mt][nt][half * 2 + 1]);
            }
        }
}

// ---------------- merged QKV fp16 GEMM + fused epilogues ----------------
__global__ void __launch_bounds__(NTHR, 2)
k_mma_qkv(const hf* __restrict__ xh, const hf* __restrict__ W,
          hf* __restrict__ vT,
          hf* __restrict__ qhmh, hf* __restrict__ qhml,
          hf* __restrict__ khmh, hf* __restrict__ khml,
          const float* __restrict__ cosb, const float* __restrict__ sinb,
          const float* __restrict__ qs, const float* __restrict__ ks)
{
    extern __shared__ char dyn[];
    const int m0 = blockIdx.y * BM, n0 = blockIdx.x * BN;
    float acc[4][4][4];
    mma_compute_f16(dyn, xh, W, DIN, DIN, m0, n0, acc);

    const int lane = threadIdx.x & 31, wid = threadIdx.x >> 5;
    const int wm = wid & 1, wn = wid >> 1;

    if (n0 >= DOUT + DKV) {
        // ---- V tile: smem transpose -> vT[kv][hd][tok] fp16 ----
        const int kv = (n0 - DOUT - DKV) / HD;
        float* stg = reinterpret_cast<float*>(dyn);   // [128 tok][133]
#pragma unroll
        for (int mt = 0; mt < 4; mt++)
#pragma unroll
            for (int half = 0; half < 2; half++) {
                const int rl = wm * 64 + mt * 16 + (lane >> 2) + half * 8;
#pragma unroll
                for (int nt = 0; nt < 4; nt++) {
                    const int c = wn * 32 + nt * 8 + (lane & 3) * 2;
                    stg[rl * 133 + c]     = acc[mt][nt][half * 2 + 0];
                    stg[rl * 133 + c + 1] = acc[mt][nt][half * 2 + 1];
                }
            }
        __syncthreads();
        const int b = m0 >> 11, pos0 = m0 & (SS - 1);
        hf* dst = vT + (size_t)(b * KVH + kv) * HD * SS + pos0;
#pragma unroll
        for (int rr = 0; rr < 16; rr++) {
            const int r = wid * 16 + rr;              // hd row
            uint2 v;
            v.x = pack_h(__float2half_rn(stg[(lane * 4 + 0) * 133 + r]),
                         __float2half_rn(stg[(lane * 4 + 1) * 133 + r]));
            v.y = pack_h(__float2half_rn(stg[(lane * 4 + 2) * 133 + r]),
                         __float2half_rn(stg[(lane * 4 + 3) * 133 + r]));
            *reinterpret_cast<uint2*>(dst + (size_t)r * SS + lane * 4) = v;
        }
        return;
    }

    // ---- Q/K tile: rmsnorm + rope + fp16 hi/lo split, head-major ----
    const bool isQ = (n0 < DOUT);
    const float* scale = isQ ? qs : ks;
    hf* oh = isQ ? qhmh : khmh;
    hf* ol = isQ ? qhml : khml;
    const int nheads = isQ ? NH : KVH;
    const int h = (isQ ? n0 : (n0 - DOUT)) / HD;
    const float alpha = isQ ? 0.08838834764831845f : 1.0f;

    float* rsum = reinterpret_cast<float*>(dyn);                 // [128][4]
    float* stg  = reinterpret_cast<float*>(dyn + 2048);          // [128][132]

#pragma unroll
    for (int mt = 0; mt < 4; mt++)
#pragma unroll
        for (int half = 0; half < 2; half++) {
            const int rl = wm * 64 + mt * 16 + (lane >> 2) + half * 8;
            float part = 0.f;
#pragma unroll
            for (int nt = 0; nt < 4; nt++) {
                const float vx = acc[mt][nt][half * 2 + 0];
                const float vy = acc[mt][nt][half * 2 + 1];
                part += vx * vx + vy * vy;
            }
            part += __shfl_xor_sync(0xffffffffu, part, 1);
            part += __shfl_xor_sync(0xffffffffu, part, 2);
            if ((lane & 3) == 0) rsum[rl * 4 + wn] = part;
        }
    __syncthreads();

#pragma unroll
    for (int mt = 0; mt < 4; mt++)
#pragma unroll
        for (int half = 0; half < 2; half++) {
            const int rl = wm * 64 + mt * 16 + (lane >> 2) + half * 8;
            const float tot = rsum[rl * 4 + 0] + rsum[rl * 4 + 1] +
                              rsum[rl * 4 + 2] + rsum[rl * 4 + 3];
            const float rinv = rsqrtf(tot * (1.0f / HD) + 1e-6f) * alpha;
#pragma unroll
            for (int nt = 0; nt < 4; nt++) {
                const int c = wn * 32 + nt * 8 + (lane & 3) * 2;
                stg[rl * 132 + c]     = acc[mt][nt][half * 2 + 0] * rinv * scale[c];
                stg[rl * 132 + c + 1] = acc[mt][nt][half * 2 + 1] * rinv * scale[c + 1];
            }
        }
    __syncthreads();

#pragma unroll
    for (int mt = 0; mt < 4; mt++)
#pragma unroll
        for (int half = 0; half < 2; half++) {
            const int rl = wm * 64 + mt * 16 + (lane >> 2) + half * 8;
            const int row = m0 + rl;
            const int b = row >> 11, pos = row & (SS - 1);
#pragma unroll
            for (int nt = 0; nt < 4; nt++) {
                const int c = wn * 32 + nt * 8 + (lane & 3) * 2;
                const float xn0 = stg[rl * 132 + c];
                const float xn1 = stg[rl * 132 + c + 1];
                const int p = (c + 64) & 127;
                const float s0 = stg[rl * 132 + p];
                const float s1 = stg[rl * 132 + p + 1];
                const float rot0 = (c < 64) ? -s0 : s0;
                const float rot1 = (c < 64) ? -s1 : s1;
                const float o0 = xn0 * cosb[pos * HD + c]     + rot0 * sinb[pos * HD + c];
                const float o1 = xn1 * cosb[pos * HD + c + 1] + rot1 * sinb[pos * HD + c + 1];
                const size_t oi = ((size_t)(b * nheads + h) * SS + pos) * HD + c;
                split2h(o0, o1, oh, ol, oi);
            }
        }
}

// ---------------- fused flash attention (QK fp16x3, PV fp16x1) ----------
__global__ void __launch_bounds__(256, 1)
k_attn(const hf* __restrict__ qhp, const hf* __restrict__ qlp,
       const hf* __restrict__ khp, const hf* __restrict__ klp,
       const hf* __restrict__ vtp,
       hf* __restrict__ ctxh)
{
    extern __shared__ char dyn[];
    const uint32_t sb = smem_u32(dyn);
    hf* VsH = reinterpret_cast<hf*>(dyn);
    const int tid = threadIdx.x, lane = tid & 31, w = tid >> 5;
    const int bh = blockIdx.y, b = bh / NH, h = bh % NH;
    const int kvh = (bh % NH) / GRP;
    const int m0 = ((int)gridDim.x - 1 - (int)blockIdx.x) * FBM;
    const size_t qo = (size_t)bh * SS * HD;
    const size_t ko = (size_t)(b * KVH + kvh) * SS * HD;
    const size_t vo = (size_t)(b * KVH + kvh) * HD * SS;

#pragma unroll
    for (int it = 0; it < 8; it++) {
        const int c = tid + it * 256;
        const int row = c >> 4, col = (c & 15) * 8;
        const size_t gi = qo + (size_t)(m0 + row) * HD + col;
        cpasync16(sb + (uint32_t)(row * QSP + col) * 2, qhp + gi);
        cpasync16(sb + QBYTES + (uint32_t)(row * QSP + col) * 2, qlp + gi);
    }
    asm volatile("cp.async.commit_group;");
    asm volatile("cp.async.wait_group 0;");
    __syncthreads();

    uint32_t qfh[8][4], qfl[8][4];
    {
        const uint32_t ab = sb +
            (uint32_t)(((w * 16 + (lane & 15)) * QSP + (lane >> 4) * 8) * 2);
#pragma unroll
        for (int kk = 0; kk < 8; kk++) {
            ldm4(qfh[kk], ab + kk * 32);
            ldm4(qfl[kk], ab + QBYTES + kk * 32);
        }
    }
    __syncthreads();

    const int nb = m0 / FBN + 2;

    auto load_kv = [&](int i) {
        if (i < nb) {
            const int n0 = i * FBN;
            const uint32_t bufb = sb + (uint32_t)(i % 3) * FSTAGE;
#pragma unroll
            for (int it = 0; it < 4; it++) {
                const int c = tid + it * 256;
                const int krow = c >> 4, kcol = (c & 15) * 8;
                const size_t gk = ko + (size_t)(n0 + krow) * HD + kcol;
                cpasync16(bufb + (uint32_t)(krow * KSP + kcol) * 2, khp + gk);
                cpasync16(bufb + KTILE + (uint32_t)(krow * KSP + kcol) * 2, klp + gk);
                const int vrow = c >> 3, vc8 = (c & 7) * 8;
                cpasync16(bufb + 2 * KTILE + (uint32_t)(vrow * VSPH + vc8) * 2,
                          vtp + vo + (size_t)vrow * SS + n0 + vc8);
            }
        }
        asm volatile("cp.async.commit_group;");
    };

    load_kv(0);
    load_kv(1);

    float ctxa[16][4];
#pragma unroll
    for (int j = 0; j < 16; j++)
#pragma unroll
        for (int e = 0; e < 4; e++) ctxa[j][e] = 0.f;
    float mrow0 = -1e30f, mrow8 = -1e30f, lrow0 = 0.f, lrow8 = 0.f;

    const uint32_t kboff =
        (uint32_t)((((lane >> 4) * 8 + (lane & 7)) * KSP + ((lane >> 3) & 1) * 8) * 2);
    const int r0g = m0 + w * 16 + (lane >> 2);
    const int cquad = 2 * (lane & 3);
    const int g = lane >> 2;

    for (int i = 0; i < nb; i++) {
        asm volatile("cp.async.wait_group 1;");
        __syncthreads();
        load_kv(i + 2);                       // prefetch overlaps compute
        const uint32_t base = sb + (uint32_t)(i % 3) * FSTAGE;
        const int vwH = (int)((i % 3) * (FSTAGE / 2)) + (2 * KTILE) / 2;
        const int n0 = i * FBN;

        float s[8][4];
#pragma unroll
        for (int j = 0; j < 8; j++)
#pragma unroll
            for (int e = 0; e < 4; e++) s[j][e] = 0.f;

        const uint32_t kb = base + kboff;
#pragma unroll
        for (int kk = 0; kk < 8; kk++) {
#pragma unroll
            for (int ng = 0; ng < 4; ng++) {
                uint32_t bh4[4], bl4[4];
                const uint32_t a = kb + (uint32_t)(ng * 16 * KSP * 2) + kk * 32;
                ldm4(bh4, a);
                ldm4(bl4, a + KTILE);
                mma_f16(s[2 * ng + 0], qfh[kk], bh4 + 0);
                mma_f16(s[2 * ng + 0], qfl[kk], bh4 + 0);
                mma_f16(s[2 * ng + 0], qfh[kk], bl4 + 0);
                mma_f16(s[2 * ng + 1], qfh[kk], bh4 + 2);
                mma_f16(s[2 * ng + 1], qfl[kk], bh4 + 2);
                mma_f16(s[2 * ng + 1], qfh[kk], bl4 + 2);
            }
        }

        if (n0 + FBN - 1 > m0) {
#pragma unroll
            for (int j = 0; j < 8; j++) {
                const int col = n0 + j * 8 + cquad;
                if (col > r0g)         s[j][0] = -1e30f;
                if (col + 1 > r0g)     s[j][1] = -1e30f;
                if (col > r0g + 8)     s[j][2] = -1e30f;
                if (col + 1 > r0g + 8) s[j][3] = -1e30f;
            }
        }

        float mx0 = -1e30f, mx8 = -1e30f;
#pragma unroll
        for (int j = 0; j < 8; j++) {
            mx0 = fmaxf(mx0, fmaxf(s[j][0], s[j][1]));
            mx8 = fmaxf(mx8, fmaxf(s[j][2], s[j][3]));
        }
        mx0 = fmaxf(mx0, __shfl_xor_sync(0xffffffffu, mx0, 1));
        mx0 = fmaxf(mx0, __shfl_xor_sync(0xffffffffu, mx0, 2));
        mx8 = fmaxf(mx8, __shfl_xor_sync(0xffffffffu, mx8, 1));
        mx8 = fmaxf(mx8, __shfl_xor_sync(0xffffffffu, mx8, 2));

        const float mn0 = fmaxf(mrow0, mx0), mn8 = fmaxf(mrow8, mx8);
        const float sc0 = __expf(mrow0 - mn0), sc8 = __expf(mrow8 - mn8);
        mrow0 = mn0; mrow8 = mn8;

        float sum0 = 0.f, sum8 = 0.f;
        uint32_t ph[8][2];
#pragma unroll
        for (int j = 0; j < 8; j++) {
            const float e0 = __expf(s[j][0] - mn0);
            const float e1 = __expf(s[j][1] - mn0);
            const float e2 = __expf(s[j][2] - mn8);
            const float e3 = __expf(s[j][3] - mn8);
            sum0 += e0 + e1; sum8 += e2 + e3;
            ph[j][0] = pack_h(__float2half_rn(e0), __float2half_rn(e1));
            ph[j][1] = pack_h(__float2half_rn(e2), __float2half_rn(e3));
        }
        sum0 += __shfl_xor_sync(0xffffffffu, sum0, 1);
        sum0 += __shfl_xor_sync(0xffffffffu, sum0, 2);
        sum8 += __shfl_xor_sync(0xffffffffu, sum8, 1);
        sum8 += __shfl_xor_sync(0xffffffffu, sum8, 2);
        lrow0 = lrow0 * sc0 + sum0;
        lrow8 = lrow8 * sc8 + sum8;

#pragma unroll
        for (int j = 0; j < 16; j++) {
            ctxa[j][0] *= sc0; ctxa[j][1] *= sc0;
            ctxa[j][2] *= sc8; ctxa[j][3] *= sc8;
        }

        // PV fp16 single-term: A = exp frags, B = V[hd][tok] natural layout
#pragma unroll
        for (int t = 0; t < 4; t++) {
            const uint32_t pa[4] = { ph[2 * t][0], ph[2 * t][1],
                                     ph[2 * t + 1][0], ph[2 * t + 1][1] };
#pragma unroll
            for (int nt = 0; nt < 16; nt++) {
                const int vi = vwH + (nt * 8 + g) * VSPH + t * 16 + cquad;
                uint32_t vb[2];
                vb[0] = *reinterpret_cast<const uint32_t*>(VsH + vi);
                vb[1] = *reinterpret_cast<const uint32_t*>(VsH + vi + 8);
                mma_f16(ctxa[nt], pa, vb);
            }
        }
    }

    // epilogue: normalize + fp16 store (O-proj operand)
    const float inv0 = 1.0f / lrow0, inv8 = 1.0f / lrow8;
    const int r0 = m0 + w * 16 + (lane >> 2);
#pragma unroll
    for (int j = 0; j < 16; j++) {
        const int col = h * HD + j * 8 + cquad;
        const size_t i0 = ((size_t)b * SS + r0) * DOUT + col;
        const size_t i8 = ((size_t)b * SS + r0 + 8) * DOUT + col;
        *reinterpret_cast<uint32_t*>(ctxh + i0) =
            pack_h(__float2half_rn(ctxa[j][0] * inv0),
                   __float2half_rn(ctxa[j][1] * inv0));
        *reinterpret_cast<uint32_t*>(ctxh + i8) =
            pack_h(__float2half_rn(ctxa[j][2] * inv8),
                   __float2half_rn(ctxa[j][3] * inv8));
    }
}

// ---------------- prep kernels ----------------
__global__ void k_xhalf(const float* __restrict__ in, hf* __restrict__ outp,
                        int n)
{
    const int i = (blockIdx.x * blockDim.x + threadIdx.x) * 2;
    if (i < n) {
        float2 v = *reinterpret_cast<const float2*>(in + i);
        *reinterpret_cast<uint32_t*>(outp + i) =
            pack_h(__float2half_rn(v.x), __float2half_rn(v.y));
    }
}

// merged weight transposes -> fp16 (flat grid over Wq, Wk, Wv, Wo)
__global__ void k_wprep(const float* __restrict__ Wq, const float* __restrict__ Wk,
                        const float* __restrict__ Wv, const float* __restrict__ Wo,
                        hf* __restrict__ WTh, hf* __restrict__ WoTh)
{
    __shared__ float t[32][33];
    int bid = blockIdx.x;
    const float* src; hf* dst; int ldin, ldout, nbx;
    if (bid < 4096)      { src = Wq; dst = WTh; ldin = DOUT; ldout = DIN; nbx = 64; }
    else if (bid < 5120) { bid -= 4096; src = Wk; dst = WTh + (size_t)DOUT * DIN;
                           ldin = DKV; ldout = DIN; nbx = 16; }
    else if (bid < 6144) { bid -= 5120; src = Wv; dst = WTh + (size_t)(DOUT + DKV) * DIN;
                           ldin = DKV; ldout = DIN; nbx = 16; }
    else                 { bid -= 6144; src = Wo; dst = WoTh; ldin = DIN; ldout = DOUT; nbx = 64; }
    const int c0 = (bid % nbx) * 32, r0 = (bid / nbx) * 32;
    const int tx = threadIdx.x, ty = threadIdx.y;
#pragma unroll
    for (int i = 0; i < 32; i += 8)
        t[ty + i][tx] = src[(size_t)(r0 + ty + i) * ldin + c0 + tx];
    __syncthreads();
#pragma unroll
    for (int i = 0; i < 32; i += 8)
        dst[(size_t)(c0 + ty + i) * ldout + r0 + tx] =
            __float2half_rn(t[tx][ty + i]);
}

// ---------------- launch ----------------
extern "C" void kernel_launch(void* const* d_in, const int* in_sizes, int n_in,
                              void* d_out, int out_size)
{
    const float* x    = (const float*)d_in[0];
    const float* cosb = (const float*)d_in[2];
    const float* sinb = (const float*)d_in[3];
    const float* Wq   = (const float*)d_in[4];
    const float* Wk   = (const float*)d_in[5];
    const float* Wv   = (const float*)d_in[6];
    const float* Wo   = (const float*)d_in[7];
    const float* qs   = (const float*)d_in[8];
    const float* ks   = (const float*)d_in[9];
    float* out = (float*)d_out;

    hf *xh, *WTh, *WoTh, *qhmh, *qhml, *khmh, *khml, *vTh, *ctxh;
    cudaGetSymbolAddress((void**)&xh,   g_xh);
    cudaGetSymbolAddress((void**)&WTh,  g_WTh);
    cudaGetSymbolAddress((void**)&WoTh, g_WoTh);
    cudaGetSymbolAddress((void**)&qhmh, g_qhmh);
    cudaGetSymbolAddress((void**)&qhml, g_qhml);
    cudaGetSymbolAddress((void**)&khmh, g_khmh);
    cudaGetSymbolAddress((void**)&khml, g_khml);
    cudaGetSymbolAddress((void**)&vTh,  g_vTh);
    cudaGetSymbolAddress((void**)&ctxh, g_ctxh);

    cudaFuncSetAttribute(k_mma_qkv, cudaFuncAttributeMaxDynamicSharedMemorySize, QKV_SMEM);
    cudaFuncSetAttribute(k_mma_o,   cudaFuncAttributeMaxDynamicSharedMemorySize, DSMEM);
    cudaFuncSetAttribute(k_attn,    cudaFuncAttributeMaxDynamicSharedMemorySize, FSMEM);

    // Prep: merged fp16 weight transposes + fp16 round of x
    k_wprep<<<10240, dim3(32, 8)>>>(Wq, Wk, Wv, Wo, WTh, WoTh);
    k_xhalf<<<(BS * DIN / 2 + 255) / 256, 256>>>(x, xh, BS * DIN);

    // Merged QKV projection (fp16 single): Q/K -> normrope+split, V -> vT
    k_mma_qkv<<<dim3(NQKV / BN, BS / BM), NTHR, QKV_SMEM>>>(
        xh, WTh, vTh, qhmh, qhml, khmh, khml, cosb, sinb, qs, ks);

    // Fused flash attention (QK fp16x3, PV fp16x1; 3-stage pipeline)
    k_attn<<<dim3(SS / FBM, BB * NH), 256, FSMEM>>>(
        qhmh, qhml, khmh, khml, vTh, ctxh);

    // Output projection (fp16 single)
    k_mma_o<<<dim3(DIN / BN, BS / BM), NTHR, DSMEM>>>(ctxh, WoTh, out);
}